// round 2
// baseline (speedup 1.0000x reference)
#include <cuda_runtime.h>

#define NT 25            // edge types
#define NMAX 50176       // node capacity (N=50000)

__device__ float g_h [NMAX * 16];
__device__ float g_h2[NMAX * 16];
__device__ float g_agg[NMAX * 16];
__device__ int   g_deg[NMAX];
__device__ float g_pool[64 * 16];
__device__ int   g_pcnt[64];

// ---------------------------------------------------------------- zeroing
__global__ void zero_kernel(int nagg, int N) {
    int i = blockIdx.x * blockDim.x + threadIdx.x;
    if (i < nagg)    g_agg[i]  = 0.f;
    if (i < N)       g_deg[i]  = 0;
    if (i < 64 * 16) g_pool[i] = 0.f;
    if (i < 64)      g_pcnt[i] = 0;
}

// ---------------------------------------------------------------- degree
__global__ void deg_kernel(const int* __restrict__ edst, int E) {
    int e = blockIdx.x * blockDim.x + threadIdx.x;
    if (e < E) atomicAdd(&g_deg[edst[e]], 1);
}

// ---------------------------------------------------------------- fused edge NN + message + scatter
// 16-lane group per edge; lane owns output column o. Per-column edge-NN
// params live in registers (amortized over grid-stride edge loop); only the
// per-type embedding (edge-dependent) is read from padded shared memory.
template <int IN, int OUT>
__global__ __launch_bounds__(256)
void edge_kernel(const float* __restrict__ xext, int xsel,
                 const float* __restrict__ ef,
                 const int*   __restrict__ etype,
                 const int*   __restrict__ esrc,
                 const int*   __restrict__ edst,
                 const float* __restrict__ emb,
                 const float* __restrict__ wh,
                 const float* __restrict__ bh,
                 const float* __restrict__ wg,
                 const float* __restrict__ bg,
                 int E)
{
    constexpr int D  = IN * OUT;
    constexpr int DP = D + 4;                       // pad: avoid cross-group bank aliasing
    __shared__ float s_emb[NT * DP];
    for (int j = threadIdx.x; j < NT * D; j += blockDim.x)
        s_emb[(j / D) * DP + (j % D)] = emb[j];
    __syncthreads();

    const float* x = (xsel == 0) ? xext : (xsel == 1 ? g_h : g_h2);

    int lane = threadIdx.x & 31;
    int o    = lane & 15;
    bool act = (o < OUT);
    int oc   = act ? o : 0;

    // register-resident per-column params (reused across all edges this thread touches)
    float a0[IN], a1[IN], a2[IN], b0[IN], b1[IN], b2[IN];
#pragma unroll
    for (int i = 0; i < IN; i++) {
        int k = i * OUT + oc;
        a0[i] = wh[k]; a1[i] = wh[D + k]; a2[i] = bh[k];
        b0[i] = wg[k]; b1[i] = wg[D + k]; b2[i] = bg[k];
    }

    int group   = (blockIdx.x * blockDim.x + threadIdx.x) >> 4;
    int ngroups = (gridDim.x * blockDim.x) >> 4;

    for (int e = group; e < E; e += ngroups) {
        int   et  = etype[e];
        int   s   = esrc[e];
        int   d   = edst[e];
        float ef0 = ef[2 * e];
        float ef1 = ef[2 * e + 1];
        float xv  = (o < IN) ? x[s * 16 + o] : 0.f;   // coalesced 64B row gather
        const float* eb = &s_emb[et * DP + oc];

        float acc = 0.f;
#pragma unroll
        for (int i = 0; i < IN; i++) {
            float xi = __shfl_sync(0xffffffffu, xv, i, 16);
            float hh = fmaf(ef0, a0[i], fmaf(ef1, a1[i], a2[i]));
            float gg = fmaf(ef0, b0[i], fmaf(ef1, b1[i], b2[i]));
            float w  = fmaxf(fmaf(eb[i * OUT], hh, gg), 0.f);
            acc = fmaf(xi, w, acc);
        }
        if (act) atomicAdd(&g_agg[d * 16 + o], acc);
    }
}

// ---------------------------------------------------------------- node update: relu(agg/deg + x@root + bias)
template <int IN, int OUT>
__global__ void node_kernel(const float* __restrict__ xext, int xsel, int osel,
                            const float* __restrict__ root,
                            const float* __restrict__ bias,
                            int N)
{
    const float* x    = (xsel == 0) ? xext : (xsel == 1 ? g_h : g_h2);
    float*       hout = (osel == 1) ? g_h : g_h2;

    int idx = blockIdx.x * blockDim.x + threadIdx.x;
    if (idx >= N * OUT) return;
    int n = idx / OUT, o = idx - n * OUT;

    float a = g_agg[n * 16 + o];
    g_agg[n * 16 + o] = 0.f;                 // leave agg zeroed for next layer/replay
    float inv = 1.f / (float)max(g_deg[n], 1);
    float acc = fmaf(a, inv, __ldg(&bias[o]));
#pragma unroll
    for (int i = 0; i < IN; i++)
        acc = fmaf(x[n * 16 + i], __ldg(&root[i * OUT + o]), acc);
    hout[n * 16 + o] = fmaxf(acc, 0.f);
}

// ---------------------------------------------------------------- pooling (scatter-mean over cell_type==1)
__global__ void pool_kernel(const int* __restrict__ ctype,
                            const int* __restrict__ bids, int N) {
    int idx = blockIdx.x * blockDim.x + threadIdx.x;
    if (idx >= N * 16) return;
    int n = idx >> 4, o = idx & 15;
    if (ctype[n] == 1) {
        int b = bids[n];
        atomicAdd(&g_pool[b * 16 + o], g_h[n * 16 + o]);
        if (o == 0) atomicAdd(&g_pcnt[b], 1);
    }
}

__global__ void final_kernel(float* __restrict__ out, int n) {
    int idx = blockIdx.x * blockDim.x + threadIdx.x;
    if (idx < n) {
        int b = idx >> 4;
        out[idx] = g_pool[idx] / (float)max(g_pcnt[b], 1);
    }
}

// ---------------------------------------------------------------- launch
extern "C" void kernel_launch(void* const* d_in, const int* in_sizes, int n_in,
                              void* d_out, int out_size)
{
    // Disambiguate metadata ordering:
    //   setup-dict order:  [2],[3],[4] are the three E-length int arrays (equal sizes)
    //   signature order :  [2]=emb1 (4000), [3]=wh1 (320) -> unequal
    bool setup_order = (in_sizes[2] == in_sizes[3]) && (in_sizes[3] == in_sizes[4]);

    const float* x     = (const float*)d_in[0];
    const float* efeat = (const float*)d_in[1];
    const int *etype, *esrc, *edst, *ctype, *bids;
    const float *emb[3], *wh[3], *bhp[3], *wg[3], *bgp[3], *root[3], *bias[3];
    int pbase, eidx, cidx;

    if (setup_order) {
        etype = (const int*)d_in[2];  esrc = (const int*)d_in[3];  edst = (const int*)d_in[4];
        ctype = (const int*)d_in[5];  bids = (const int*)d_in[6];
        pbase = 8; eidx = 2; cidx = 5;
    } else {
        etype = (const int*)d_in[23]; esrc = (const int*)d_in[24]; edst = (const int*)d_in[25];
        ctype = (const int*)d_in[26]; bids = (const int*)d_in[27];
        pbase = 2; eidx = 23; cidx = 26;
    }
    for (int l = 0; l < 3; l++) {
        int b0 = pbase + l * 7;
        emb[l]  = (const float*)d_in[b0];
        wh[l]   = (const float*)d_in[b0 + 1];
        bhp[l]  = (const float*)d_in[b0 + 2];
        wg[l]   = (const float*)d_in[b0 + 3];
        bgp[l]  = (const float*)d_in[b0 + 4];
        root[l] = (const float*)d_in[b0 + 5];
        bias[l] = (const float*)d_in[b0 + 6];
    }
    int E = in_sizes[eidx];
    int N = in_sizes[cidx];
    float* out = (float*)d_out;

    zero_kernel<<<(N * 16 + 255) / 256, 256>>>(N * 16, N);
    deg_kernel<<<(E + 255) / 256, 256>>>(edst, E);

    const int EB = 296, ET = 256;   // fixed grid -> grid-stride edges, params amortized

    // layer 1: 16 -> 10
    edge_kernel<16, 10><<<EB, ET>>>(x, 0, efeat, etype, esrc, edst,
                                    emb[0], wh[0], bhp[0], wg[0], bgp[0], E);
    node_kernel<16, 10><<<(N * 10 + 255) / 256, 256>>>(x, 0, 1, root[0], bias[0], N);

    // layer 2: 10 -> 10
    edge_kernel<10, 10><<<EB, ET>>>(x, 1, efeat, etype, esrc, edst,
                                    emb[1], wh[1], bhp[1], wg[1], bgp[1], E);
    node_kernel<10, 10><<<(N * 10 + 255) / 256, 256>>>(x, 1, 2, root[1], bias[1], N);

    // layer 3: 10 -> 16
    edge_kernel<10, 16><<<EB, ET>>>(x, 2, efeat, etype, esrc, edst,
                                    emb[2], wh[2], bhp[2], wg[2], bgp[2], E);
    node_kernel<10, 16><<<(N * 16 + 255) / 256, 256>>>(x, 2, 1, root[2], bias[2], N);

    pool_kernel<<<(N * 16 + 255) / 256, 256>>>(ctype, bids, N);
    final_kernel<<<1, 256>>>(out, out_size);
}

// round 3
// speedup vs baseline: 1.0798x; 1.0798x over previous
#include <cuda_runtime.h>

#define NT 25            // edge types
#define NMAX 50176       // node capacity (N=50000)

__device__ float g_h [NMAX * 16];
__device__ float g_h2[NMAX * 16];
__device__ float g_agg[NMAX * 16];
__device__ int   g_deg[NMAX];
__device__ float g_pool[64 * 16];
__device__ int   g_pcnt[64];

// ---------------------------------------------------------------- fused edge NN + message + scatter
// 16-lane group per edge; lane owns output column o. Per-column edge-NN
// params live in registers (amortized over grid-stride edge loop); only the
// per-type embedding stays in padded shared memory (1 LDS per k-step).
// Software-pipelined: next edge's metadata + x row prefetched before the
// inner loop so the random-row L2 gather (~250cyc) overlaps compute.
template <int IN, int OUT, bool DEG>
__global__ __launch_bounds__(256)
void edge_kernel(const float* __restrict__ xext, int xsel,
                 const float2* __restrict__ ef,
                 const int*   __restrict__ etype,
                 const int*   __restrict__ esrc,
                 const int*   __restrict__ edst,
                 const float* __restrict__ emb,
                 const float* __restrict__ wh,
                 const float* __restrict__ bh,
                 const float* __restrict__ wg,
                 const float* __restrict__ bg,
                 int E)
{
    constexpr int D  = IN * OUT;
    constexpr int DP = D + 16;                 // shift banks per edge type
    __shared__ float s_emb[NT * DP];
    for (int j = threadIdx.x; j < NT * D; j += blockDim.x)
        s_emb[(j / D) * DP + (j % D)] = emb[j];
    __syncthreads();

    const float* x = (xsel == 0) ? xext : (xsel == 1 ? g_h : g_h2);

    int o  = threadIdx.x & 15;
    int oc = (o < OUT) ? o : 0;

    float a0[IN], a1[IN], a2[IN], b0[IN], b1[IN], b2[IN];
#pragma unroll
    for (int i = 0; i < IN; i++) {
        int k = i * OUT + oc;
        a0[i] = __ldg(&wh[k]); a1[i] = __ldg(&wh[D + k]); a2[i] = __ldg(&bh[k]);
        b0[i] = __ldg(&wg[k]); b1[i] = __ldg(&wg[D + k]); b2[i] = __ldg(&bg[k]);
    }

    int group = (blockIdx.x * blockDim.x + threadIdx.x) >> 4;
    int ng    = (gridDim.x * blockDim.x) >> 4;

    int e = group;
    int et = 0, s = 0, d = 0; float ef0 = 0.f, ef1 = 0.f, xv = 0.f;
    if (e < E) {
        et = etype[e]; s = esrc[e]; d = edst[e];
        float2 f = ef[e]; ef0 = f.x; ef1 = f.y;
        xv = x[s * 16 + o];
    }
    while (e < E) {
        // prefetch next edge
        int e2 = e + ng;
        int et2 = 0, s2 = 0, d2 = 0; float ef02 = 0.f, ef12 = 0.f, xv2 = 0.f;
        if (e2 < E) {
            et2 = etype[e2]; s2 = esrc[e2]; d2 = edst[e2];
            float2 f = ef[e2]; ef02 = f.x; ef12 = f.y;
            xv2 = x[s2 * 16 + o];
        }

        const float* eb = &s_emb[et * DP + oc];
        float acc0 = 0.f, acc1 = 0.f;
#pragma unroll
        for (int i = 0; i < IN; i += 2) {       // IN is even (16 or 10)
            {
                float xi = __shfl_sync(0xffffffffu, xv, i, 16);
                float hh = fmaf(ef0, a0[i], fmaf(ef1, a1[i], a2[i]));
                float gg = fmaf(ef0, b0[i], fmaf(ef1, b1[i], b2[i]));
                float w  = fmaxf(fmaf(eb[i * OUT], hh, gg), 0.f);
                acc0 = fmaf(xi, w, acc0);
            }
            {
                float xi = __shfl_sync(0xffffffffu, xv, i + 1, 16);
                float hh = fmaf(ef0, a0[i + 1], fmaf(ef1, a1[i + 1], a2[i + 1]));
                float gg = fmaf(ef0, b0[i + 1], fmaf(ef1, b1[i + 1], b2[i + 1]));
                float w  = fmaxf(fmaf(eb[(i + 1) * OUT], hh, gg), 0.f);
                acc1 = fmaf(xi, w, acc1);
            }
        }
        if (o < OUT) atomicAdd(&g_agg[d * 16 + o], acc0 + acc1);
        if (DEG && o == 0) atomicAdd(&g_deg[d], 1);

        e = e2; et = et2; s = s2; d = d2; ef0 = ef02; ef1 = ef12; xv = xv2;
    }
}

// ---------------------------------------------------------------- node update: relu(agg/deg + x@root + bias)
// 16 lanes per node, fully coalesced, straight-line. Reads-then-zeroes g_agg
// so the next layer / next graph replay sees zeros without a zero kernel.
// POOL variant fuses the gated scatter-mean pooling (layer 3) and zeroes deg.
template <int IN, int OUT, bool POOL>
__global__ __launch_bounds__(256)
void node_kernel(const float* __restrict__ xext, int xsel, int osel,
                 const float* __restrict__ root,
                 const float* __restrict__ bias,
                 const int*   __restrict__ ctype,
                 const int*   __restrict__ bids,
                 int N)
{
    int idx  = blockIdx.x * blockDim.x + threadIdx.x;
    int n    = idx >> 4;
    int lane = idx & 15;
    bool valid = (n < N);
    if (!valid) n = 0;                       // keep warp converged for shfl

    const float* x    = (xsel == 0) ? xext : (xsel == 1 ? g_h : g_h2);
    float*       hout = (osel == 1) ? g_h : g_h2;

    int lc = (lane < OUT) ? lane : 0;
    float rreg[IN];
#pragma unroll
    for (int i = 0; i < IN; i++) rreg[i] = __ldg(&root[i * OUT + lc]);
    float bv = __ldg(&bias[lc]);

    float xv = x[n * 16 + lane];
    float a  = g_agg[n * 16 + lane];
    if (valid) g_agg[n * 16 + lane] = 0.f;   // self-cleaning for next layer/replay
    int dg   = g_deg[n];
    float inv = __frcp_rn((float)(dg > 0 ? dg : 1));

    float acc = fmaf(a, inv, bv);
#pragma unroll
    for (int i = 0; i < IN; i++)
        acc = fmaf(__shfl_sync(0xffffffffu, xv, i, 16), rreg[i], acc);
    acc = fmaxf(acc, 0.f);

    if (POOL) {
        if (valid && ctype[n] == 1) {
            int b = bids[n];
            atomicAdd(&g_pool[b * 16 + lane], acc);
            if (lane == 0) atomicAdd(&g_pcnt[b], 1);
        }
        if (valid && lane == 0) g_deg[n] = 0;   // reset for next replay
    } else {
        if (valid && lane < OUT) hout[n * 16 + lane] = acc;
    }
}

// ---------------------------------------------------------------- final: divide + emit, then reset pool state
__global__ void final_kernel(float* __restrict__ out, int nsz) {
    int idx = threadIdx.x;
    if (idx < nsz) {
        int b = idx >> 4;
        int c = g_pcnt[b];
        out[idx] = g_pool[idx] / (float)(c > 0 ? c : 1);
    }
    __syncthreads();
    for (int j = idx; j < 64 * 16; j += blockDim.x) g_pool[j] = 0.f;
    if (idx < 64) g_pcnt[idx] = 0;
}

// ---------------------------------------------------------------- launch
extern "C" void kernel_launch(void* const* d_in, const int* in_sizes, int n_in,
                              void* d_out, int out_size)
{
    // Disambiguate metadata ordering:
    //   setup-dict order:  [2],[3],[4] are the three E-length int arrays (equal sizes)
    //   signature order :  [2]=emb1 (4000), [3]=wh1 (320) -> unequal
    bool setup_order = (in_sizes[2] == in_sizes[3]) && (in_sizes[3] == in_sizes[4]);

    const float* x     = (const float*)d_in[0];
    const float* efeat = (const float*)d_in[1];
    const int *etype, *esrc, *edst, *ctype, *bids;
    const float *emb[3], *wh[3], *bhp[3], *wg[3], *bgp[3], *root[3], *bias[3];
    int pbase, eidx, cidx;

    if (setup_order) {
        etype = (const int*)d_in[2];  esrc = (const int*)d_in[3];  edst = (const int*)d_in[4];
        ctype = (const int*)d_in[5];  bids = (const int*)d_in[6];
        pbase = 8; eidx = 2; cidx = 5;
    } else {
        etype = (const int*)d_in[23]; esrc = (const int*)d_in[24]; edst = (const int*)d_in[25];
        ctype = (const int*)d_in[26]; bids = (const int*)d_in[27];
        pbase = 2; eidx = 23; cidx = 26;
    }
    for (int l = 0; l < 3; l++) {
        int b0 = pbase + l * 7;
        emb[l]  = (const float*)d_in[b0];
        wh[l]   = (const float*)d_in[b0 + 1];
        bhp[l]  = (const float*)d_in[b0 + 2];
        wg[l]   = (const float*)d_in[b0 + 3];
        bgp[l]  = (const float*)d_in[b0 + 4];
        root[l] = (const float*)d_in[b0 + 5];
        bias[l] = (const float*)d_in[b0 + 6];
    }
    int E = in_sizes[eidx];
    int N = in_sizes[cidx];
    float* out = (float*)d_out;

    const int EB = 296, ET = 256;               // fixed grid: grid-stride edges
    int NB = (N * 16 + 255) / 256;

    // layer 1: 16 -> 10  (also accumulates degree)
    edge_kernel<16, 10, true ><<<EB, ET>>>(x, 0, (const float2*)efeat, etype, esrc, edst,
                                           emb[0], wh[0], bhp[0], wg[0], bgp[0], E);
    node_kernel<16, 10, false><<<NB, 256>>>(x, 0, 1, root[0], bias[0], nullptr, nullptr, N);

    // layer 2: 10 -> 10
    edge_kernel<10, 10, false><<<EB, ET>>>(x, 1, (const float2*)efeat, etype, esrc, edst,
                                           emb[1], wh[1], bhp[1], wg[1], bgp[1], E);
    node_kernel<10, 10, false><<<NB, 256>>>(x, 1, 2, root[1], bias[1], nullptr, nullptr, N);

    // layer 3: 10 -> 16  (node kernel fuses pooling, zeroes deg)
    edge_kernel<10, 16, false><<<EB, ET>>>(x, 2, (const float2*)efeat, etype, esrc, edst,
                                           emb[2], wh[2], bhp[2], wg[2], bgp[2], E);
    node_kernel<10, 16, true ><<<NB, 256>>>(x, 2, 0, root[2], bias[2], ctype, bids, N);

    final_kernel<<<1, 256>>>(out, out_size);
}

// round 4
// speedup vs baseline: 1.0969x; 1.0158x over previous
#include <cuda_runtime.h>

#define NT 25            // edge types
#define NMAX 50176       // node capacity (N=50000)

__device__ float g_h [NMAX * 16];
__device__ float g_h2[NMAX * 16];
__device__ float g_agg[NMAX * 16];
__device__ int   g_deg[NMAX];
__device__ float g_pool[64 * 16];
__device__ int   g_pcnt[64];

// ---------------------------------------------------------------- fused edge NN + message + scatter
template <int IN, int OUT, bool DEG>
__global__ __launch_bounds__(256)
void edge_kernel(const float* __restrict__ xext, int xsel,
                 const float2* __restrict__ ef,
                 const int*   __restrict__ etype,
                 const int*   __restrict__ esrc,
                 const int*   __restrict__ edst,
                 const float* __restrict__ emb,
                 const float* __restrict__ wh,
                 const float* __restrict__ bh,
                 const float* __restrict__ wg,
                 const float* __restrict__ bg,
                 int E)
{
    constexpr int D  = IN * OUT;
    constexpr int DP = D + 16;
    __shared__ float s_emb[NT * DP];
    for (int j = threadIdx.x; j < NT * D; j += blockDim.x)
        s_emb[(j / D) * DP + (j % D)] = emb[j];
    __syncthreads();

    const float* x = (xsel == 0) ? xext : (xsel == 1 ? g_h : g_h2);

    int o  = threadIdx.x & 15;
    int oc = (o < OUT) ? o : 0;

    // per-column edge-NN params in registers, amortized over grid-stride loop
    float a0[IN], a1[IN], a2[IN], b0[IN], b1[IN], b2[IN];
#pragma unroll
    for (int i = 0; i < IN; i++) {
        int k = i * OUT + oc;
        a0[i] = __ldg(&wh[k]); a1[i] = __ldg(&wh[D + k]); a2[i] = __ldg(&bh[k]);
        b0[i] = __ldg(&wg[k]); b1[i] = __ldg(&wg[D + k]); b2[i] = __ldg(&bg[k]);
    }

    int group = (blockIdx.x * blockDim.x + threadIdx.x) >> 4;
    int ng    = (gridDim.x * blockDim.x) >> 4;

    int e = group;
    int et = 0, s = 0, d = 0; float ef0 = 0.f, ef1 = 0.f, xv = 0.f;
    if (e < E) {
        et = etype[e]; s = esrc[e]; d = edst[e];
        float2 f = ef[e]; ef0 = f.x; ef1 = f.y;
        xv = x[s * 16 + o];
    }
    while (e < E) {
        // software pipeline: prefetch next edge while computing this one
        int e2 = e + ng;
        int et2 = 0, s2 = 0, d2 = 0; float ef02 = 0.f, ef12 = 0.f, xv2 = 0.f;
        if (e2 < E) {
            et2 = etype[e2]; s2 = esrc[e2]; d2 = edst[e2];
            float2 f = ef[e2]; ef02 = f.x; ef12 = f.y;
            xv2 = x[s2 * 16 + o];
        }

        const float* eb = &s_emb[et * DP + oc];
        float acc0 = 0.f, acc1 = 0.f;
#pragma unroll
        for (int i = 0; i < IN; i += 2) {
            {
                float xi = __shfl_sync(0xffffffffu, xv, i, 16);
                float hh = fmaf(ef0, a0[i], fmaf(ef1, a1[i], a2[i]));
                float gg = fmaf(ef0, b0[i], fmaf(ef1, b1[i], b2[i]));
                float w  = fmaxf(fmaf(eb[i * OUT], hh, gg), 0.f);
                acc0 = fmaf(xi, w, acc0);
            }
            {
                float xi = __shfl_sync(0xffffffffu, xv, i + 1, 16);
                float hh = fmaf(ef0, a0[i + 1], fmaf(ef1, a1[i + 1], a2[i + 1]));
                float gg = fmaf(ef0, b0[i + 1], fmaf(ef1, b1[i + 1], b2[i + 1]));
                float w  = fmaxf(fmaf(eb[(i + 1) * OUT], hh, gg), 0.f);
                acc1 = fmaf(xi, w, acc1);
            }
        }
        if (o < OUT) atomicAdd(&g_agg[d * 16 + o], acc0 + acc1);
        if (DEG && o == 0) atomicAdd(&g_deg[d], 1);

        e = e2; et = et2; s = s2; d = d2; ef0 = ef02; ef1 = ef12; xv = xv2;
    }
}

// ---------------------------------------------------------------- node update: relu(agg/deg + x@root + bias)
// 16 lanes per node. NO shuffles: each lane loads the full x row via float4
// (L1 broadcast across the node's lanes), FMA tree on independent registers.
// Reads-then-zeroes g_agg so the next layer / graph replay sees zeros.
template <int IN, int OUT, bool POOL>
__global__ __launch_bounds__(256)
void node_kernel(const float* __restrict__ xext, int xsel, int osel,
                 const float* __restrict__ root,
                 const float* __restrict__ bias,
                 const int*   __restrict__ ctype,
                 const int*   __restrict__ bids,
                 int N)
{
    int idx  = blockIdx.x * blockDim.x + threadIdx.x;
    int n    = idx >> 4;
    int lane = idx & 15;
    if (n >= N) return;

    const float* x    = (xsel == 0) ? xext : (xsel == 1 ? g_h : g_h2);
    float*       hout = (osel == 1) ? g_h : g_h2;

    int lc = (lane < OUT) ? lane : 0;

    // independent loads: x row (float4), agg, deg, params — high MLP
    const float4* xr = (const float4*)(x + n * 16);
    float xv[IN];
    {
        float4 v0 = __ldg(&xr[0]);
        float4 v1 = __ldg(&xr[1]);
        xv[0] = v0.x; xv[1] = v0.y; xv[2] = v0.z; xv[3] = v0.w;
        xv[4] = v1.x; xv[5] = v1.y; xv[6] = v1.z; xv[7] = v1.w;
        if constexpr (IN == 16) {
            float4 v2 = __ldg(&xr[2]);
            float4 v3 = __ldg(&xr[3]);
            xv[8]  = v2.x; xv[9]  = v2.y; xv[10] = v2.z; xv[11] = v2.w;
            xv[12] = v3.x; xv[13] = v3.y; xv[14] = v3.z; xv[15] = v3.w;
        } else {
            float2 v2 = __ldg(&((const float2*)xr)[4]);
            xv[8] = v2.x; xv[9] = v2.y;
        }
    }

    float a = g_agg[n * 16 + lane];
    g_agg[n * 16 + lane] = 0.f;              // self-cleaning
    int dg = g_deg[n];
    float inv = __frcp_rn((float)(dg > 0 ? dg : 1));

    float acc0 = fmaf(a, inv, __ldg(&bias[lc]));
    float acc1 = 0.f, acc2 = 0.f, acc3 = 0.f;
#pragma unroll
    for (int i = 0; i + 3 < IN; i += 4) {
        acc0 = fmaf(xv[i],     __ldg(&root[(i)     * OUT + lc]), acc0);
        acc1 = fmaf(xv[i + 1], __ldg(&root[(i + 1) * OUT + lc]), acc1);
        acc2 = fmaf(xv[i + 2], __ldg(&root[(i + 2) * OUT + lc]), acc2);
        acc3 = fmaf(xv[i + 3], __ldg(&root[(i + 3) * OUT + lc]), acc3);
    }
    if constexpr (IN % 4 != 0) {             // IN=10 tail: i=8,9
        acc1 = fmaf(xv[IN - 2], __ldg(&root[(IN - 2) * OUT + lc]), acc1);
        acc2 = fmaf(xv[IN - 1], __ldg(&root[(IN - 1) * OUT + lc]), acc2);
    }
    float acc = fmaxf((acc0 + acc1) + (acc2 + acc3), 0.f);

    if (POOL) {
        if (ctype[n] == 1) {
            int b = bids[n];
            atomicAdd(&g_pool[b * 16 + lane], acc);
            if (lane == 0) atomicAdd(&g_pcnt[b], 1);
        }
        if (lane == 0) g_deg[n] = 0;         // reset for next replay
    } else {
        if (lane < OUT) hout[n * 16 + lane] = acc;
    }
}

// ---------------------------------------------------------------- final: divide + emit, then reset pool state
__global__ void final_kernel(float* __restrict__ out, int nsz) {
    int idx = threadIdx.x;
    if (idx < nsz) {
        int b = idx >> 4;
        int c = g_pcnt[b];
        out[idx] = g_pool[idx] / (float)(c > 0 ? c : 1);
    }
    __syncthreads();
    for (int j = idx; j < 64 * 16; j += blockDim.x) g_pool[j] = 0.f;
    if (idx < 64) g_pcnt[idx] = 0;
}

// ---------------------------------------------------------------- launch
extern "C" void kernel_launch(void* const* d_in, const int* in_sizes, int n_in,
                              void* d_out, int out_size)
{
    bool setup_order = (in_sizes[2] == in_sizes[3]) && (in_sizes[3] == in_sizes[4]);

    const float* x     = (const float*)d_in[0];
    const float* efeat = (const float*)d_in[1];
    const int *etype, *esrc, *edst, *ctype, *bids;
    const float *emb[3], *wh[3], *bhp[3], *wg[3], *bgp[3], *root[3], *bias[3];
    int pbase, eidx, cidx;

    if (setup_order) {
        etype = (const int*)d_in[2];  esrc = (const int*)d_in[3];  edst = (const int*)d_in[4];
        ctype = (const int*)d_in[5];  bids = (const int*)d_in[6];
        pbase = 8; eidx = 2; cidx = 5;
    } else {
        etype = (const int*)d_in[23]; esrc = (const int*)d_in[24]; edst = (const int*)d_in[25];
        ctype = (const int*)d_in[26]; bids = (const int*)d_in[27];
        pbase = 2; eidx = 23; cidx = 26;
    }
    for (int l = 0; l < 3; l++) {
        int b0 = pbase + l * 7;
        emb[l]  = (const float*)d_in[b0];
        wh[l]   = (const float*)d_in[b0 + 1];
        bhp[l]  = (const float*)d_in[b0 + 2];
        wg[l]   = (const float*)d_in[b0 + 3];
        bgp[l]  = (const float*)d_in[b0 + 4];
        root[l] = (const float*)d_in[b0 + 5];
        bias[l] = (const float*)d_in[b0 + 6];
    }
    int E = in_sizes[eidx];
    int N = in_sizes[cidx];
    float* out = (float*)d_out;

    const int EB = 592, ET = 256;            // 4 blocks/SM: more latency hiding
    int NB = (N * 16 + 255) / 256;

    // layer 1: 16 -> 10  (also accumulates degree)
    edge_kernel<16, 10, true ><<<EB, ET>>>(x, 0, (const float2*)efeat, etype, esrc, edst,
                                           emb[0], wh[0], bhp[0], wg[0], bgp[0], E);
    node_kernel<16, 10, false><<<NB, 256>>>(x, 0, 1, root[0], bias[0], nullptr, nullptr, N);

    // layer 2: 10 -> 10
    edge_kernel<10, 10, false><<<EB, ET>>>(x, 1, (const float2*)efeat, etype, esrc, edst,
                                           emb[1], wh[1], bhp[1], wg[1], bgp[1], E);
    node_kernel<10, 10, false><<<NB, 256>>>(x, 1, 2, root[1], bias[1], nullptr, nullptr, N);

    // layer 3: 10 -> 16  (fused pooling, zeroes deg)
    edge_kernel<10, 16, false><<<EB, ET>>>(x, 2, (const float2*)efeat, etype, esrc, edst,
                                           emb[2], wh[2], bhp[2], wg[2], bgp[2], E);
    node_kernel<10, 16, true ><<<NB, 256>>>(x, 2, 0, root[2], bias[2], ctype, bids, N);

    final_kernel<<<1, 256>>>(out, out_size);
}